// round 9
// baseline (speedup 1.0000x reference)
#include <cuda_runtime.h>
#include <cstdint>

#define BB 16
#define NPTS 2048
#define MM 16
#define SS 128
#define NBLK 32                 // n-blocks per batch
#define BN 64                   // n per CTA
#define XT 16                   // x threads (n direction)
#define YT 16                   // y threads (s direction)
#define NPT 4                   // n per thread (2 packed pairs)
#define SPT 8                   // s per thread per m
#define GRID1 (BB * NBLK)       // 512
#define K2_BLOCKS 32

static __device__ float g_partmin[BB * MM * NBLK * SS];  // [bm][nblk][s]  4MB
static __device__ float g_colmean[BB * MM];
static __device__ float g_part1[GRID1];
static __device__ unsigned g_ticket = 0;

// ---- packed f32x2 helpers (add/mul/fma only on sm_103a) ----
#define ADD2(d, a, b)    asm("add.rn.f32x2 %0, %1, %2;" : "=l"(d) : "l"(a), "l"(b))
#define FMA2(d, a, b, c) asm("fma.rn.f32x2 %0, %1, %2, %3;" : "=l"(d) : "l"(a), "l"(b), "l"(c))
#define PACK2(d, lo, hi) asm("mov.b64 %0, {%1, %2};" : "=l"(d) \
                             : "r"(__float_as_uint(lo)), "r"(__float_as_uint(hi)))
#define UNPACK2(lo, hi, s) do { unsigned _ul, _uh;                                  \
    asm("mov.b64 {%0, %1}, %2;" : "=r"(_ul), "=r"(_uh) : "l"(s));                   \
    (lo) = __uint_as_float(_ul); (hi) = __uint_as_float(_uh); } while (0)

// ---------------------------------------------------------------------------
// Kernel 1 (fused distances + sort): one CTA per (b, 64-n block), all 16 m.
//  - pcl slice is contiguous -> coalesced smem stage (no transpose kernel).
//  - per m: packed-f32x2 hot loop (thread owns 4 n x 8 s), per-s min via
//    half-warp __reduce_min_sync; 3-way parallel epilogue on disjoint thread
//    ranges (dmin combine | prim[m+1] prefetch | g_partmin flush).
//  - final: in-CTA odd-even sort of d1[n][0..15] + stick-breaking partial.
// ---------------------------------------------------------------------------
__global__ __launch_bounds__(256, 4) void k1(const float* __restrict__ pcl,
                                             const float* __restrict__ prim,
                                             const float* __restrict__ probs) {
    const int cta = blockIdx.x;
    const int b = cta >> 5;
    const int nb = cta & (NBLK - 1);
    const int n0 = nb * BN;
    const int tid = threadIdx.x;
    const int x = tid & (XT - 1);
    const int y = tid >> 4;
    const int lane = tid & 31;

    __shared__ float spcl[BN * 49];        // raw pcl rows, 48 -> 49 pad  12.5KB
    __shared__ ulonglong2 sAC[SS];         // {(-2a,-2a),(-2c,-2c)}        2KB
    __shared__ ulonglong2 sDQ[SS];         // {(-2d,-2d),(q,q)}            2KB
    __shared__ float sbufm[YT][SPT];       // per-s min over 64 n (this m) 0.5KB
    __shared__ float sredm[YT][BN + 1];    // dmin y-combine               4.1KB
    __shared__ float d1s[BN][MM + 1];      // d1[n][m]                     4.3KB
    __shared__ float sprob[MM];
    __shared__ float red[BN];

    // ---- stage A: coalesced pcl slice + prim[m=0] + probs ----
    const float* src = pcl + ((size_t)b * NPTS + n0) * (MM * 3);
#pragma unroll
    for (int kk = 0; kk < 12; kk++) {
        int j = tid + kk * 256;            // 0..3071 coalesced
        spcl[(j / 48) * 49 + (j % 48)] = src[j];
    }
    if (tid < MM) sprob[tid] = probs[b * MM + tid];
    if (tid >= 64 && tid < 128) {
        int s2 = (tid - 64) * 2;
        const float* pp = prim + ((size_t)(b * MM + 0) * SS + s2) * 3;
#pragma unroll
        for (int e = 0; e < 2; e++) {
            float a = pp[e * 3 + 0], c = pp[e * 3 + 1], d = pp[e * 3 + 2];
            float q = a * a + c * c + d * d;
            float ta = -2.0f * a, tc = -2.0f * c, td = -2.0f * d;
            unsigned long long aa, cc, dd, qq;
            PACK2(aa, ta, ta); PACK2(cc, tc, tc); PACK2(dd, td, td); PACK2(qq, q, q);
            sAC[s2 + e] = make_ulonglong2(aa, cc);
            sDQ[s2 + e] = make_ulonglong2(dd, qq);
        }
    }
    __syncthreads();

    const unsigned halfmask = 0xFFFFu << (lane & 16);

    for (int m = 0; m < MM; m++) {
        // per-thread pcl registers for this m (4 n = 2 packed pairs)
        unsigned long long nx2[2], ny2[2], nz2[2], uu2[2];
#pragma unroll
        for (int p = 0; p < 2; p++) {
            int na = x + (2 * p) * 16;
            int nbq = x + (2 * p + 1) * 16;
            const float* ra = spcl + na * 49 + m * 3;
            const float* rb = spcl + nbq * 49 + m * 3;
            float xa = ra[0], ya = ra[1], za = ra[2];
            float xb = rb[0], yb = rb[1], zb = rb[2];
            PACK2(nx2[p], xa, xb);
            PACK2(ny2[p], ya, yb);
            PACK2(nz2[p], za, zb);
            PACK2(uu2[p], xa * xa + ya * ya + za * za,
                          xb * xb + yb * yb + zb * zb);
        }
        float dmin[NPT];
#pragma unroll
        for (int j = 0; j < NPT; j++) dmin[j] = 3.4e38f;

        // ---- hot loop: 8 s x 4 n ----
#pragma unroll
        for (int k = 0; k < SPT; k++) {
            const int s = y * SPT + k;
            ulonglong2 ac = sAC[s];
            ulonglong2 dq = sDQ[s];
            unsigned long long t0, t1;
            ADD2(t0, dq.y, uu2[0]);
            FMA2(t0, ac.x, nx2[0], t0);
            FMA2(t0, ac.y, ny2[0], t0);
            FMA2(t0, dq.x, nz2[0], t0);
            ADD2(t1, dq.y, uu2[1]);
            FMA2(t1, ac.x, nx2[1], t1);
            FMA2(t1, ac.y, ny2[1], t1);
            FMA2(t1, dq.x, nz2[1], t1);
            float f0, f1, f2, f3;
            UNPACK2(f0, f1, t0);
            UNPACK2(f2, f3, t1);
            dmin[0] = fminf(dmin[0], f0);
            dmin[1] = fminf(dmin[1], f1);
            dmin[2] = fminf(dmin[2], f2);
            dmin[3] = fminf(dmin[3], f3);
            // per-s min over this thread's 4 n, then over the 16 x-threads
            float e = fmaxf(fminf(fminf(f0, f1), fminf(f2, f3)), 0.0f);
            unsigned r = __reduce_min_sync(halfmask, __float_as_uint(e));
            if ((lane & 15) == 0) sbufm[y][k] = __uint_as_float(r);
        }

        // stage dmin for the y-combine
#pragma unroll
        for (int p = 0; p < 2; p++) {
            sredm[y][x + (2 * p) * 16]     = dmin[2 * p];
            sredm[y][x + (2 * p + 1) * 16] = dmin[2 * p + 1];
        }
        __syncthreads();

        // ---- parallel epilogue on disjoint thread ranges ----
        if (tid < 64) {
            // d1[n][m] = min over the 16 y-slices
            float v = sredm[0][tid];
#pragma unroll
            for (int yy = 1; yy < YT; yy++) v = fminf(v, sredm[yy][tid]);
            d1s[tid][m] = v;
        } else if (tid < 128) {
            // prefetch prim[m+1]
            if (m + 1 < MM) {
                int s2 = (tid - 64) * 2;
                const float* pp = prim + ((size_t)(b * MM + (m + 1)) * SS + s2) * 3;
#pragma unroll
                for (int e = 0; e < 2; e++) {
                    float a = pp[e * 3 + 0], c = pp[e * 3 + 1], d = pp[e * 3 + 2];
                    float q = a * a + c * c + d * d;
                    float ta = -2.0f * a, tc = -2.0f * c, td = -2.0f * d;
                    unsigned long long aa, cc, dd, qq;
                    PACK2(aa, ta, ta); PACK2(cc, tc, tc); PACK2(dd, td, td); PACK2(qq, q, q);
                    sAC[s2 + e] = make_ulonglong2(aa, cc);
                    sDQ[s2 + e] = make_ulonglong2(dd, qq);
                }
            }
        } else {
            // flush per-s mins for this m (coalesced 512B)
            int s = tid - 128;
            g_partmin[(((size_t)(b * MM + m)) * NBLK + nb) * SS + s] =
                sbufm[s >> 3][s & 7];
        }
        __syncthreads();
    }

    // ---- sort + stick-breaking per n (threads 0..63), block partial ----
    if (tid < BN) {
        float d[MM], p[MM];
#pragma unroll
        for (int i = 0; i < MM; i++) { d[i] = d1s[tid][i]; p[i] = sprob[i]; }
#pragma unroll
        for (int r = 0; r < MM; r++) {
#pragma unroll
            for (int i = (r & 1); i + 1 < MM; i += 2) {
                if (d[i] > d[i + 1]) {
                    float td = d[i]; d[i] = d[i + 1]; d[i + 1] = td;
                    float tp = p[i]; p[i] = p[i + 1]; p[i + 1] = tp;
                }
            }
        }
        float run = 1.0f, sum = 0.0f;
#pragma unroll
        for (int i = 0; i < MM; i++) {
            sum += d[i] * p[i] * run;
            run *= (1.0f - p[i]);
        }
        red[tid] = sum;
    }
    __syncthreads();
    if (tid < 32) {
        float v = red[tid] + red[tid + 32];
#pragma unroll
        for (int off = 16; off > 0; off >>= 1)
            v += __shfl_down_sync(0xffffffffu, v, off);
        if (tid == 0) g_part1[cta] = v;
    }
}

// ---------------------------------------------------------------------------
// Kernel 2 (tail): 32 blocks.
//  Each block: 8 warps, warp per (b,m): min over the 32 n-block partials per s,
//  clamp, mean over s -> g_colmean.  Last block (fence + ticket) computes
//  areas + the final 4 scalars.
// ---------------------------------------------------------------------------
__global__ __launch_bounds__(256) void k2(const float* __restrict__ probs,
                                          const float* __restrict__ size_,
                                          float* __restrict__ out, int out_size) {
    __shared__ float red[256];
    __shared__ int is_last;

    {
        const int w = threadIdx.x >> 5;
        const int lane = threadIdx.x & 31;
        const int bm = blockIdx.x * 8 + w;
        const float* pm = g_partmin + (size_t)bm * NBLK * SS;  // [nblk][s]
        float sum = 0.0f;
#pragma unroll
        for (int i = 0; i < SS / 32; i++) {
            int s = lane + 32 * i;
            float mn = 3.4e38f;
#pragma unroll 8
            for (int nb = 0; nb < NBLK; nb++)
                mn = fminf(mn, pm[nb * SS + s]);
            if (mn >= 1e30f) mn = 0.0f;   // INF_CLAMP rule
            sum += mn;
        }
#pragma unroll
        for (int off = 16; off > 0; off >>= 1)
            sum += __shfl_down_sync(0xffffffffu, sum, off);
        if (lane == 0) g_colmean[bm] = sum * (1.0f / SS);
    }

    // ---- last-block election: final combine ----
    __threadfence();
    if (threadIdx.x == 0) {
        unsigned t = atomicAdd(&g_ticket, 1u);
        is_last = (t == K2_BLOCKS - 1);
    }
    __syncthreads();
    if (!is_last) return;

    const int tid = threadIdx.x;  // 256 == B*M
    const float FOUR_PI = 12.566370614359172f;
    __shared__ float area[256];
    __shared__ float p1_shared;
    const int b = tid >> 4;

    float s0 = size_[tid * 3 + 0];
    float s1 = size_[tid * 3 + 1];
    float s2 = size_[tid * 3 + 2];
    // sizes in [0.05, 1] -> strictly positive; fast MUFU pow is safe.
    float inner = (__powf(s0 * s1, 1.6f) + __powf(s0 * s2, 1.6f) + __powf(s1 * s2, 1.6f))
                  * (1.0f / 3.0f);
    float ar = FOUR_PI * __powf(inner, 0.625f);
    area[tid] = ar;
    __syncthreads();

    float sb = 0.0f;
#pragma unroll
    for (int j = 0; j < MM; j++) sb += area[b * MM + j];

    float contrib = g_colmean[tid] * probs[tid] * ((float)MM * ar / sb) * (1.0f / (BB * MM));

    // pcl_to_prim: reduce the 512 per-CTA partials
    red[tid] = g_part1[tid] + g_part1[tid + 256];
    __syncthreads();
    for (int off = 128; off > 0; off >>= 1) {
        if (tid < off) red[tid] += red[tid + off];
        __syncthreads();
    }
    if (tid == 0) p1_shared = red[0];
    __syncthreads();

    red[tid] = contrib;
    __syncthreads();
    for (int off = 128; off > 0; off >>= 1) {
        if (tid < off) red[tid] += red[tid + off];
        __syncthreads();
    }

    if (tid == 0) {
        float pcl_to_prim = p1_shared * (1.0f / ((float)BB * (float)NPTS));
        float prim_to_pcl = red[0];
        float total = pcl_to_prim + prim_to_pcl;
        if (out_size > 0) out[0] = total;
        if (out_size > 1) out[1] = pcl_to_prim;
        if (out_size > 2) out[2] = prim_to_pcl;
        if (out_size > 3) out[3] = 0.0f;
        g_ticket = 0;   // reset for the next graph replay
    }
}

extern "C" void kernel_launch(void* const* d_in, const int* in_sizes, int n_in,
                              void* d_out, int out_size) {
    const float* pcl   = (const float*)d_in[0];  // (B, N, M, 3)
    const float* prim  = (const float*)d_in[1];  // (B, M, S, 3)
    const float* size_ = (const float*)d_in[2];  // (B, M, 3)
    const float* probs = (const float*)d_in[3];  // (B, M)

    k1<<<GRID1, 256>>>(pcl, prim, probs);
    k2<<<K2_BLOCKS, 256>>>(probs, size_, (float*)d_out, out_size);
}

// round 10
// speedup vs baseline: 1.3429x; 1.3429x over previous
#include <cuda_runtime.h>
#include <cstdint>

#define BB 16
#define NPTS 2048
#define MM 16
#define SS 128
#define NSPLIT 4
#define NCHUNK (NPTS / NSPLIT)        // 512 n per CTA
#define TX 64                          // threads in n direction
#define TY 4                           // threads in s direction
#define NCNT (NCHUNK / TX)             // 8 n per thread
#define NPAIR (NCNT / 2)               // 4 packed pairs
#define SCNT (SS / TY)                 // 32 s per thread
#define SPAD 257                       // padded float row stride
#define K2_SORT_BLOCKS ((BB * NPTS) / 256)   // 128
#define K2_CM_BLOCKS ((BB * MM) / 8)         // 32
#define K2_TOTAL (K2_SORT_BLOCKS + K2_CM_BLOCKS)

static __device__ float4 g_pclT[BB * MM * NPTS];           // [b][m][n] = (-2x,-2y,-2z,|x|^2)
static __device__ float g_d1T[BB * MM * NPTS];             // [b][m][n] min-over-s
static __device__ float g_partmin[BB * MM * NSPLIT * SS];  // per (bm,chunk), per-s min-over-chunk
static __device__ float g_colmean[BB * MM];                // mean_s min_n (clamped)
static __device__ float g_part1[K2_SORT_BLOCKS];           // pcl_to_prim partials
static __device__ unsigned g_ticket = 0;                   // last-block election counter

// ---- packed f32x2 helpers (add/mul/fma only — no packed min on sm_103a) ----
#define ADD2(d, a, b)    asm("add.rn.f32x2 %0, %1, %2;" : "=l"(d) : "l"(a), "l"(b))
#define FMA2(d, a, b, c) asm("fma.rn.f32x2 %0, %1, %2, %3;" : "=l"(d) : "l"(a), "l"(b), "l"(c))
#define PACK2(d, lo, hi) asm("mov.b64 %0, {%1, %2};" : "=l"(d) \
                             : "r"(__float_as_uint(lo)), "r"(__float_as_uint(hi)))
#define UNPACK2(lo, hi, s) do { unsigned _ul, _uh;                                  \
    asm("mov.b64 {%0, %1}, %2;" : "=r"(_ul), "=r"(_uh) : "l"(s));                   \
    (lo) = __uint_as_float(_ul); (hi) = __uint_as_float(_uh); } while (0)

// ---------------------------------------------------------------------------
// Kernel 0: smem-tiled transpose with float4 loads (3 LDG.128 per thread
// instead of 12 scalar LDG.32). 512 blocks x 64 n-rows.
// pcl (B,N,M,3) -> pclT[b][m][n] float4 (-2x,-2y,-2z,|x|^2).
// ---------------------------------------------------------------------------
__global__ __launch_bounds__(256) void k0(const float* __restrict__ pcl) {
    const int blk = blockIdx.x;
    const int b = blk >> 5;
    const int n0 = (blk & 31) * 64;
    const int tid = threadIdx.x;

    __shared__ float sm[64 * 49];   // 64 rows of 48 floats, padded to 49

    // 64 rows x 48 floats = 768 float4; 3 per thread, fully coalesced.
    const float4* src = (const float4*)(pcl + ((size_t)b * NPTS + n0) * (MM * 3));
#pragma unroll
    for (int k = 0; k < 3; k++) {
        int j4 = tid + k * 256;            // float4 index 0..767
        float4 v = src[j4];
        int e = j4 * 4;                    // element index (multiple of 4)
        int row = e / 48;
        int col = e - row * 48;            // 0..44, stays within one row (48 % 4 == 0)
        float* dst = sm + row * 49 + col;
        dst[0] = v.x; dst[1] = v.y; dst[2] = v.z; dst[3] = v.w;
    }
    __syncthreads();

    const int m = tid >> 4;
    const int l = tid & 15;
#pragma unroll
    for (int r = 0; r < 4; r++) {
        int nl = r * 16 + l;
        const float* row = sm + nl * 49 + m * 3;
        float X = row[0], Y = row[1], Z = row[2];
        g_pclT[(size_t)(b * MM + m) * NPTS + n0 + nl] =
            make_float4(-2.0f * X, -2.0f * Y, -2.0f * Z, X * X + Y * Y + Z * Z);
    }
}

// ---------------------------------------------------------------------------
// Kernel 1 (R5-proven form): one CTA per (b, m, n-chunk). Packed f32x2
// distances; dmin in regs (scalar mins); per-s min -> one STS per iteration.
// __launch_bounds__(256,3) keeps regs low enough for 3 CTAs/SM.
// ---------------------------------------------------------------------------
__global__ __launch_bounds__(TX * TY, 3) void k1(const float* __restrict__ prim) {
    const int bid = blockIdx.x;            // = bm * NSPLIT + chunk
    const int chunk = bid & (NSPLIT - 1);
    const int bm = bid >> 2;
    const int b = bm >> 4;
    const int m = bm & 15;
    const int tid = threadIdx.x;
    const int x = tid & (TX - 1);
    const int y = tid >> 6;                // 0..3

    __shared__ ulonglong2 sAC[SS];         // {(a,a),(c,c)}   2KB
    __shared__ ulonglong2 sDQ[SS];         // {(d,d),(q,q)}   2KB
    __shared__ float sminS[SCNT * SPAD];   // [k][tid], padded rows  ~33KB
    __shared__ float sred[TY * NCHUNK];    // dmin combine    8KB

    const float* pp = prim + (size_t)(b * MM + m) * SS * 3;
    for (int s = tid; s < SS; s += TX * TY) {
        float a = pp[3 * s + 0];
        float c = pp[3 * s + 1];
        float d = pp[3 * s + 2];
        float q = a * a + c * c + d * d;
        unsigned long long aa, cc, dd, qq;
        PACK2(aa, a, a); PACK2(cc, c, c); PACK2(dd, d, d); PACK2(qq, q, q);
        sAC[s] = make_ulonglong2(aa, cc);
        sDQ[s] = make_ulonglong2(dd, qq);
    }
    __syncthreads();

    // Coalesced prologue: 8 float4 loads (lane = consecutive n).
    const float4* pt = g_pclT + (size_t)bm * NPTS + chunk * NCHUNK;
    unsigned long long nx2[NPAIR], ny2[NPAIR], nz2[NPAIR], uu2[NPAIR];
    float dmin[NCNT];
#pragma unroll
    for (int p = 0; p < NPAIR; p++) {
        float4 v0 = pt[(2 * p) * TX + x];
        float4 v1 = pt[(2 * p + 1) * TX + x];
        PACK2(nx2[p], v0.x, v1.x);
        PACK2(ny2[p], v0.y, v1.y);
        PACK2(nz2[p], v0.z, v1.z);
        PACK2(uu2[p], v0.w, v1.w);
        dmin[2 * p] = 3.4e38f;
        dmin[2 * p + 1] = 3.4e38f;
    }

    // ---- hot loop: 32 s x 8 n per thread; dmin in regs, smin -> one STS ----
#pragma unroll
    for (int k = 0; k < SCNT; k++) {
        const int s = y * SCNT + k;
        ulonglong2 ac = sAC[s];
        ulonglong2 dq = sDQ[s];
        float pm[NPAIR];
#pragma unroll
        for (int p = 0; p < NPAIR; p++) {
            unsigned long long t;
            ADD2(t, dq.y, uu2[p]);             // q + |x|^2
            FMA2(t, ac.x, nx2[p], t);          // -2 a x
            FMA2(t, ac.y, ny2[p], t);
            FMA2(t, dq.x, nz2[p], t);
            float f0, f1;
            UNPACK2(f0, f1, t);
            dmin[2 * p]     = fminf(dmin[2 * p], f0);
            dmin[2 * p + 1] = fminf(dmin[2 * p + 1], f1);
            pm[p] = fminf(f0, f1);
        }
        sminS[k * SPAD + tid] =
            fminf(fminf(pm[0], pm[1]), fminf(pm[2], pm[3]));
    }

    // ---- epilogue 1: dmin — combine the 4 y-slices via smem ----
#pragma unroll
    for (int j = 0; j < NCNT; j++) sred[y * NCHUNK + j * TX + x] = dmin[j];
    __syncthreads();

    float* d1out = g_d1T + (size_t)bm * NPTS + chunk * NCHUNK;
#pragma unroll
    for (int r = 0; r < 2; r++) {
        int nl = r * 256 + tid;
        float v = fminf(fminf(sred[0 * NCHUNK + nl], sred[1 * NCHUNK + nl]),
                        fminf(sred[2 * NCHUNK + nl], sred[3 * NCHUNK + nl]));
        d1out[nl] = v;
    }

    // ---- epilogue 2: smin — per s, min over its 64 contributing threads ----
    if (tid < SS) {
        const int kk = tid & 31;
        const int yy = tid >> 5;
        const float* rowp = sminS + kk * SPAD + 64 * yy;
        float v = rowp[0];
#pragma unroll
        for (int i = 1; i < 64; i++) v = fminf(v, rowp[i]);
        g_partmin[(size_t)bid * SS + tid] = v;
    }
}

// ---------------------------------------------------------------------------
// Kernel 2 (fused with the final combine):
//  blocks [0,128): per (b,n) odd-even sort of M=16 (dist,prob), stick-breaking
//  sum, block partial -> g_part1.
//  blocks [128,160): colmean -> g_colmean.
//  LAST block to finish (fence + atomic ticket) computes areas + final scalars.
// ---------------------------------------------------------------------------
__global__ __launch_bounds__(256) void k2(const float* __restrict__ probs,
                                          const float* __restrict__ size_,
                                          float* __restrict__ out, int out_size) {
    __shared__ float red[256];
    __shared__ int is_last;

    if (blockIdx.x < K2_SORT_BLOCKS) {
        const int idx = blockIdx.x * 256 + threadIdx.x;  // < B*N
        const int b = idx >> 11;
        const int n = idx & (NPTS - 1);

        float d[MM], p[MM];
#pragma unroll
        for (int i = 0; i < MM; i++)
            d[i] = g_d1T[(size_t)(b * MM + i) * NPTS + n];
#pragma unroll
        for (int i = 0; i < MM; i++) p[i] = probs[b * MM + i];

#pragma unroll
        for (int r = 0; r < MM; r++) {
#pragma unroll
            for (int i = (r & 1); i + 1 < MM; i += 2) {
                if (d[i] > d[i + 1]) {
                    float td = d[i]; d[i] = d[i + 1]; d[i + 1] = td;
                    float tp = p[i]; p[i] = p[i + 1]; p[i + 1] = tp;
                }
            }
        }

        float run = 1.0f, sum = 0.0f;
#pragma unroll
        for (int i = 0; i < MM; i++) {
            sum += d[i] * p[i] * run;
            run *= (1.0f - p[i]);
        }

        red[threadIdx.x] = sum;
        __syncthreads();
        for (int off = 128; off > 0; off >>= 1) {
            if (threadIdx.x < off) red[threadIdx.x] += red[threadIdx.x + off];
            __syncthreads();
        }
        if (threadIdx.x == 0) g_part1[blockIdx.x] = red[0];
    } else {
        const int bb = blockIdx.x - K2_SORT_BLOCKS;     // 0..31
        const int w = threadIdx.x >> 5;
        const int lane = threadIdx.x & 31;
        const int bm = bb * 8 + w;

        const float* pm = g_partmin + (size_t)bm * NSPLIT * SS;
        float sum = 0.0f;
#pragma unroll
        for (int i = 0; i < SS / 32; i++) {
            int s = lane + 32 * i;
            float mn = fminf(fminf(pm[0 * SS + s], pm[1 * SS + s]),
                             fminf(pm[2 * SS + s], pm[3 * SS + s]));
            if (mn >= 1e30f) mn = 0.0f;   // INF_CLAMP rule
            sum += mn;
        }
#pragma unroll
        for (int off = 16; off > 0; off >>= 1)
            sum += __shfl_down_sync(0xffffffffu, sum, off);
        if (lane == 0) g_colmean[bm] = sum * (1.0f / SS);
    }

    // ---- last-block election: the final combine ----
    __threadfence();
    if (threadIdx.x == 0) {
        unsigned t = atomicAdd(&g_ticket, 1u);
        is_last = (t == K2_TOTAL - 1);
    }
    __syncthreads();
    if (!is_last) return;

    const int tid = threadIdx.x;  // 256 == B*M
    const float FOUR_PI = 12.566370614359172f;
    __shared__ float area[256];
    __shared__ float p1_shared;
    const int b = tid >> 4;

    float s0 = size_[tid * 3 + 0];
    float s1 = size_[tid * 3 + 1];
    float s2 = size_[tid * 3 + 2];
    // sizes in [0.05, 1] -> strictly positive; fast MUFU pow is safe.
    float inner = (__powf(s0 * s1, 1.6f) + __powf(s0 * s2, 1.6f) + __powf(s1 * s2, 1.6f))
                  * (1.0f / 3.0f);
    float ar = FOUR_PI * __powf(inner, 0.625f);
    area[tid] = ar;
    __syncthreads();

    float sb = 0.0f;
#pragma unroll
    for (int j = 0; j < MM; j++) sb += area[b * MM + j];

    float contrib = g_colmean[tid] * probs[tid] * ((float)MM * ar / sb) * (1.0f / (BB * MM));

    red[tid] = (tid < K2_SORT_BLOCKS) ? g_part1[tid] : 0.0f;
    __syncthreads();
    for (int off = 128; off > 0; off >>= 1) {
        if (tid < off) red[tid] += red[tid + off];
        __syncthreads();
    }
    if (tid == 0) p1_shared = red[0];
    __syncthreads();

    red[tid] = contrib;
    __syncthreads();
    for (int off = 128; off > 0; off >>= 1) {
        if (tid < off) red[tid] += red[tid + off];
        __syncthreads();
    }

    if (tid == 0) {
        float pcl_to_prim = p1_shared * (1.0f / ((float)BB * (float)NPTS));
        float prim_to_pcl = red[0];
        float total = pcl_to_prim + prim_to_pcl;
        if (out_size > 0) out[0] = total;
        if (out_size > 1) out[1] = pcl_to_prim;
        if (out_size > 2) out[2] = prim_to_pcl;
        if (out_size > 3) out[3] = 0.0f;
        g_ticket = 0;   // reset for the next graph replay
    }
}

extern "C" void kernel_launch(void* const* d_in, const int* in_sizes, int n_in,
                              void* d_out, int out_size) {
    const float* pcl   = (const float*)d_in[0];  // (B, N, M, 3)
    const float* prim  = (const float*)d_in[1];  // (B, M, S, 3)
    const float* size_ = (const float*)d_in[2];  // (B, M, 3)
    const float* probs = (const float*)d_in[3];  // (B, M)

    k0<<<BB * (NPTS / 64), 256>>>(pcl);
    k1<<<BB * MM * NSPLIT, TX * TY>>>(prim);
    k2<<<K2_TOTAL, 256>>>(probs, size_, (float*)d_out, out_size);
}

// round 11
// speedup vs baseline: 1.8140x; 1.3509x over previous
#include <cuda_runtime.h>
#include <cstdint>

#define BB 16
#define NPTS 2048
#define MM 16
#define SS 128
#define NSPLIT 4
#define NCHUNK (NPTS / NSPLIT)        // 512 n per CTA
#define TX 64                          // threads in n direction
#define TY 4                           // threads in s direction
#define NCNT (NCHUNK / TX)             // 8 n per thread
#define NPAIR (NCNT / 2)               // 4 packed pairs
#define SCNT (SS / TY)                 // 32 s per thread
#define SPAD 257                       // padded float row stride
#define K2_SORT_BLOCKS ((BB * NPTS) / 256)   // 128
#define K2_CM_BLOCKS ((BB * MM) / 8)         // 32
#define K2_TOTAL (K2_SORT_BLOCKS + K2_CM_BLOCKS)

static __device__ float g_d1T[BB * MM * NPTS];             // [b][m][n] min-over-s
static __device__ float g_partmin[BB * MM * NSPLIT * SS];  // per (bm,chunk), per-s min-over-chunk
static __device__ float g_colmean[BB * MM];                // mean_s min_n (clamped)
static __device__ float g_part1[K2_SORT_BLOCKS];           // pcl_to_prim partials
static __device__ unsigned g_ticket = 0;                   // last-block election counter

// ---- packed f32x2 helpers (add/mul/fma only — no packed min on sm_103a) ----
#define ADD2(d, a, b)    asm("add.rn.f32x2 %0, %1, %2;" : "=l"(d) : "l"(a), "l"(b))
#define FMA2(d, a, b, c) asm("fma.rn.f32x2 %0, %1, %2, %3;" : "=l"(d) : "l"(a), "l"(b), "l"(c))
#define PACK2(d, lo, hi) asm("mov.b64 %0, {%1, %2};" : "=l"(d) \
                             : "r"(__float_as_uint(lo)), "r"(__float_as_uint(hi)))
#define UNPACK2(lo, hi, s) do { unsigned _ul, _uh;                                  \
    asm("mov.b64 {%0, %1}, %2;" : "=r"(_ul), "=r"(_uh) : "l"(s));                   \
    (lo) = __uint_as_float(_ul); (hi) = __uint_as_float(_uh); } while (0)

// ---------------------------------------------------------------------------
// Kernel 1: one CTA per (b, m, n-chunk). Self-staging: the CTA copies its
// pcl slice (512 n x 3 floats for its m; strided gather, L2-resident) into
// smem (reusing the epilogue's sred buffer), builds packed registers, then
// runs the R10-proven packed-f32x2 hot loop. No transpose kernel, no pclT
// round-trip.
// ---------------------------------------------------------------------------
__global__ __launch_bounds__(TX * TY, 3) void k1(const float* __restrict__ pcl,
                                                 const float* __restrict__ prim) {
    const int bid = blockIdx.x;            // = bm * NSPLIT + chunk
    const int chunk = bid & (NSPLIT - 1);
    const int bm = bid >> 2;
    const int b = bm >> 4;
    const int m = bm & 15;
    const int tid = threadIdx.x;
    const int x = tid & (TX - 1);
    const int y = tid >> 6;                // 0..3

    __shared__ ulonglong2 sAC[SS];         // {(a,a),(c,c)}   2KB
    __shared__ ulonglong2 sDQ[SS];         // {(d,d),(q,q)}   2KB
    __shared__ float sminS[SCNT * SPAD];   // [k][tid], padded rows  ~33KB
    __shared__ float sred[TY * NCHUNK];    // dmin combine / pcl stage  8KB

    // ---- stage prim (s-side) ----
    const float* pp = prim + (size_t)(b * MM + m) * SS * 3;
    for (int s = tid; s < SS; s += TX * TY) {
        float a = pp[3 * s + 0];
        float c = pp[3 * s + 1];
        float d = pp[3 * s + 2];
        float q = a * a + c * c + d * d;
        unsigned long long aa, cc, dd, qq;
        PACK2(aa, a, a); PACK2(cc, c, c); PACK2(dd, d, d); PACK2(qq, q, q);
        sAC[s] = make_ulonglong2(aa, cc);
        sDQ[s] = make_ulonglong2(dd, qq);
    }

    // ---- stage pcl slice (n-side) into sred: spcl[nl*3 + c] ----
    // src element for local n: pcl[b][chunk*512 + nl][m][c] = base + nl*48 + c
    {
        const float* src = pcl + ((size_t)(b * NPTS + chunk * NCHUNK)) * (MM * 3) + m * 3;
        float* spcl = sred;
#pragma unroll
        for (int kk = 0; kk < 6; kk++) {
            int j = tid + kk * 256;        // 0..1535
            int n = j / 3;
            int c = j - 3 * n;
            spcl[j] = src[n * 48 + c];
        }
    }
    __syncthreads();

    // ---- build packed registers from smem (stride-3 reads: conflict-free) ----
    const float* spcl = sred;
    unsigned long long nx2[NPAIR], ny2[NPAIR], nz2[NPAIR], uu2[NPAIR];
    float dmin[NCNT];
#pragma unroll
    for (int p = 0; p < NPAIR; p++) {
        int na = ((2 * p) * TX + x) * 3;
        int nb = ((2 * p + 1) * TX + x) * 3;
        float xa = spcl[na], ya = spcl[na + 1], za = spcl[na + 2];
        float xb = spcl[nb], yb = spcl[nb + 1], zb = spcl[nb + 2];
        PACK2(nx2[p], -2.0f * xa, -2.0f * xb);
        PACK2(ny2[p], -2.0f * ya, -2.0f * yb);
        PACK2(nz2[p], -2.0f * za, -2.0f * zb);
        PACK2(uu2[p], xa * xa + ya * ya + za * za,
                      xb * xb + yb * yb + zb * zb);
        dmin[2 * p] = 3.4e38f;
        dmin[2 * p + 1] = 3.4e38f;
    }
    __syncthreads();   // everyone done reading spcl before sred is rewritten

    // ---- hot loop: 32 s x 8 n per thread; dmin in regs, smin -> one STS ----
#pragma unroll
    for (int k = 0; k < SCNT; k++) {
        const int s = y * SCNT + k;
        ulonglong2 ac = sAC[s];
        ulonglong2 dq = sDQ[s];
        float pm[NPAIR];
#pragma unroll
        for (int p = 0; p < NPAIR; p++) {
            unsigned long long t;
            ADD2(t, dq.y, uu2[p]);             // q + |x|^2
            FMA2(t, ac.x, nx2[p], t);          // -2 a x
            FMA2(t, ac.y, ny2[p], t);
            FMA2(t, dq.x, nz2[p], t);
            float f0, f1;
            UNPACK2(f0, f1, t);
            dmin[2 * p]     = fminf(dmin[2 * p], f0);
            dmin[2 * p + 1] = fminf(dmin[2 * p + 1], f1);
            pm[p] = fminf(f0, f1);
        }
        sminS[k * SPAD + tid] =
            fminf(fminf(pm[0], pm[1]), fminf(pm[2], pm[3]));
    }

    // ---- epilogue 1: dmin — combine the 4 y-slices via smem ----
#pragma unroll
    for (int j = 0; j < NCNT; j++) sred[y * NCHUNK + j * TX + x] = dmin[j];
    __syncthreads();

    float* d1out = g_d1T + (size_t)bm * NPTS + chunk * NCHUNK;
#pragma unroll
    for (int r = 0; r < 2; r++) {
        int nl = r * 256 + tid;
        float v = fminf(fminf(sred[0 * NCHUNK + nl], sred[1 * NCHUNK + nl]),
                        fminf(sred[2 * NCHUNK + nl], sred[3 * NCHUNK + nl]));
        d1out[nl] = v;
    }

    // ---- epilogue 2: smin — per s, min over its 64 contributing threads ----
    if (tid < SS) {
        const int kk = tid & 31;
        const int yy = tid >> 5;
        const float* rowp = sminS + kk * SPAD + 64 * yy;
        float v = rowp[0];
#pragma unroll
        for (int i = 1; i < 64; i++) v = fminf(v, rowp[i]);
        g_partmin[(size_t)bid * SS + tid] = v;
    }
}

// ---------------------------------------------------------------------------
// Kernel 2 (fused with the final combine):
//  blocks [0,128): per (b,n) odd-even sort of M=16 (dist,prob), stick-breaking
//  sum, block partial -> g_part1.
//  blocks [128,160): colmean -> g_colmean.
//  LAST block to finish (fence + atomic ticket) computes areas + final scalars.
// ---------------------------------------------------------------------------
__global__ __launch_bounds__(256) void k2(const float* __restrict__ probs,
                                          const float* __restrict__ size_,
                                          float* __restrict__ out, int out_size) {
    __shared__ float red[256];
    __shared__ int is_last;

    if (blockIdx.x < K2_SORT_BLOCKS) {
        const int idx = blockIdx.x * 256 + threadIdx.x;  // < B*N
        const int b = idx >> 11;
        const int n = idx & (NPTS - 1);

        float d[MM], p[MM];
#pragma unroll
        for (int i = 0; i < MM; i++)
            d[i] = g_d1T[(size_t)(b * MM + i) * NPTS + n];
#pragma unroll
        for (int i = 0; i < MM; i++) p[i] = probs[b * MM + i];

#pragma unroll
        for (int r = 0; r < MM; r++) {
#pragma unroll
            for (int i = (r & 1); i + 1 < MM; i += 2) {
                if (d[i] > d[i + 1]) {
                    float td = d[i]; d[i] = d[i + 1]; d[i + 1] = td;
                    float tp = p[i]; p[i] = p[i + 1]; p[i + 1] = tp;
                }
            }
        }

        float run = 1.0f, sum = 0.0f;
#pragma unroll
        for (int i = 0; i < MM; i++) {
            sum += d[i] * p[i] * run;
            run *= (1.0f - p[i]);
        }

        red[threadIdx.x] = sum;
        __syncthreads();
        for (int off = 128; off > 0; off >>= 1) {
            if (threadIdx.x < off) red[threadIdx.x] += red[threadIdx.x + off];
            __syncthreads();
        }
        if (threadIdx.x == 0) g_part1[blockIdx.x] = red[0];
    } else {
        const int bb = blockIdx.x - K2_SORT_BLOCKS;     // 0..31
        const int w = threadIdx.x >> 5;
        const int lane = threadIdx.x & 31;
        const int bm = bb * 8 + w;

        const float* pm = g_partmin + (size_t)bm * NSPLIT * SS;
        float sum = 0.0f;
#pragma unroll
        for (int i = 0; i < SS / 32; i++) {
            int s = lane + 32 * i;
            float mn = fminf(fminf(pm[0 * SS + s], pm[1 * SS + s]),
                             fminf(pm[2 * SS + s], pm[3 * SS + s]));
            if (mn >= 1e30f) mn = 0.0f;   // INF_CLAMP rule
            sum += mn;
        }
#pragma unroll
        for (int off = 16; off > 0; off >>= 1)
            sum += __shfl_down_sync(0xffffffffu, sum, off);
        if (lane == 0) g_colmean[bm] = sum * (1.0f / SS);
    }

    // ---- last-block election: the final combine ----
    __threadfence();
    if (threadIdx.x == 0) {
        unsigned t = atomicAdd(&g_ticket, 1u);
        is_last = (t == K2_TOTAL - 1);
    }
    __syncthreads();
    if (!is_last) return;

    const int tid = threadIdx.x;  // 256 == B*M
    const float FOUR_PI = 12.566370614359172f;
    __shared__ float area[256];
    __shared__ float p1_shared;
    const int b = tid >> 4;

    float s0 = size_[tid * 3 + 0];
    float s1 = size_[tid * 3 + 1];
    float s2 = size_[tid * 3 + 2];
    // sizes in [0.05, 1] -> strictly positive; fast MUFU pow is safe.
    float inner = (__powf(s0 * s1, 1.6f) + __powf(s0 * s2, 1.6f) + __powf(s1 * s2, 1.6f))
                  * (1.0f / 3.0f);
    float ar = FOUR_PI * __powf(inner, 0.625f);
    area[tid] = ar;
    __syncthreads();

    float sb = 0.0f;
#pragma unroll
    for (int j = 0; j < MM; j++) sb += area[b * MM + j];

    float contrib = g_colmean[tid] * probs[tid] * ((float)MM * ar / sb) * (1.0f / (BB * MM));

    red[tid] = (tid < K2_SORT_BLOCKS) ? g_part1[tid] : 0.0f;
    __syncthreads();
    for (int off = 128; off > 0; off >>= 1) {
        if (tid < off) red[tid] += red[tid + off];
        __syncthreads();
    }
    if (tid == 0) p1_shared = red[0];
    __syncthreads();

    red[tid] = contrib;
    __syncthreads();
    for (int off = 128; off > 0; off >>= 1) {
        if (tid < off) red[tid] += red[tid + off];
        __syncthreads();
    }

    if (tid == 0) {
        float pcl_to_prim = p1_shared * (1.0f / ((float)BB * (float)NPTS));
        float prim_to_pcl = red[0];
        float total = pcl_to_prim + prim_to_pcl;
        if (out_size > 0) out[0] = total;
        if (out_size > 1) out[1] = pcl_to_prim;
        if (out_size > 2) out[2] = prim_to_pcl;
        if (out_size > 3) out[3] = 0.0f;
        g_ticket = 0;   // reset for the next graph replay
    }
}

extern "C" void kernel_launch(void* const* d_in, const int* in_sizes, int n_in,
                              void* d_out, int out_size) {
    const float* pcl   = (const float*)d_in[0];  // (B, N, M, 3)
    const float* prim  = (const float*)d_in[1];  // (B, M, S, 3)
    const float* size_ = (const float*)d_in[2];  // (B, M, 3)
    const float* probs = (const float*)d_in[3];  // (B, M)

    k1<<<BB * MM * NSPLIT, TX * TY>>>(pcl, prim);
    k2<<<K2_TOTAL, 256>>>(probs, size_, (float*)d_out, out_size);
}

// round 12
// speedup vs baseline: 1.8312x; 1.0094x over previous
#include <cuda_runtime.h>
#include <cstdint>

#define BB 16
#define NPTS 2048
#define MM 16
#define SS 128
#define NSPLIT 4
#define NCHUNK (NPTS / NSPLIT)        // 512 n per CTA
#define TX 64                          // threads in n direction
#define TY 4                           // threads in s direction
#define NCNT (NCHUNK / TX)             // 8 n per thread
#define NPAIR (NCNT / 2)               // 4 packed pairs
#define SCNT (SS / TY)                 // 32 s per thread
#define SPAD 257                       // padded float row stride
#define K2_SORT_BLOCKS ((BB * NPTS) / 256)   // 128
#define K2_CM_BLOCKS ((BB * MM) / 8)         // 32
#define K2_TOTAL (K2_SORT_BLOCKS + K2_CM_BLOCKS)

static __device__ float g_d1T[BB * MM * NPTS];             // [b][m][n] min-over-s
static __device__ float g_partmin[BB * MM * NSPLIT * SS];  // per (bm,chunk), per-s min-over-chunk
static __device__ float g_colmean[BB * MM];                // mean_s min_n (clamped)
static __device__ float g_part1[K2_SORT_BLOCKS];           // pcl_to_prim partials
static __device__ unsigned g_ticket = 0;                   // last-block election counter

// ---- packed f32x2 helpers (add/mul/fma only — no packed min on sm_103a) ----
#define ADD2(d, a, b)    asm("add.rn.f32x2 %0, %1, %2;" : "=l"(d) : "l"(a), "l"(b))
#define FMA2(d, a, b, c) asm("fma.rn.f32x2 %0, %1, %2, %3;" : "=l"(d) : "l"(a), "l"(b), "l"(c))
#define PACK2(d, lo, hi) asm("mov.b64 %0, {%1, %2};" : "=l"(d) \
                             : "r"(__float_as_uint(lo)), "r"(__float_as_uint(hi)))
#define UNPACK2(lo, hi, s) do { unsigned _ul, _uh;                                  \
    asm("mov.b64 {%0, %1}, %2;" : "=r"(_ul), "=r"(_uh) : "l"(s));                   \
    (lo) = __uint_as_float(_ul); (hi) = __uint_as_float(_uh); } while (0)

// ---------------------------------------------------------------------------
// Kernel 1 (R11-proven, unchanged): one CTA per (b, m, n-chunk). Self-staging
// pcl slice into smem; packed-f32x2 hot loop; dual epilogue.
// ---------------------------------------------------------------------------
__global__ __launch_bounds__(TX * TY, 3) void k1(const float* __restrict__ pcl,
                                                 const float* __restrict__ prim) {
    const int bid = blockIdx.x;            // = bm * NSPLIT + chunk
    const int chunk = bid & (NSPLIT - 1);
    const int bm = bid >> 2;
    const int b = bm >> 4;
    const int m = bm & 15;
    const int tid = threadIdx.x;
    const int x = tid & (TX - 1);
    const int y = tid >> 6;                // 0..3

    __shared__ ulonglong2 sAC[SS];         // {(a,a),(c,c)}   2KB
    __shared__ ulonglong2 sDQ[SS];         // {(d,d),(q,q)}   2KB
    __shared__ float sminS[SCNT * SPAD];   // [k][tid], padded rows  ~33KB
    __shared__ float sred[TY * NCHUNK];    // dmin combine / pcl stage  8KB

    // ---- stage prim (s-side) ----
    const float* pp = prim + (size_t)(b * MM + m) * SS * 3;
    for (int s = tid; s < SS; s += TX * TY) {
        float a = pp[3 * s + 0];
        float c = pp[3 * s + 1];
        float d = pp[3 * s + 2];
        float q = a * a + c * c + d * d;
        unsigned long long aa, cc, dd, qq;
        PACK2(aa, a, a); PACK2(cc, c, c); PACK2(dd, d, d); PACK2(qq, q, q);
        sAC[s] = make_ulonglong2(aa, cc);
        sDQ[s] = make_ulonglong2(dd, qq);
    }

    // ---- stage pcl slice (n-side) into sred: spcl[nl*3 + c] ----
    {
        const float* src = pcl + ((size_t)(b * NPTS + chunk * NCHUNK)) * (MM * 3) + m * 3;
        float* spcl = sred;
#pragma unroll
        for (int kk = 0; kk < 6; kk++) {
            int j = tid + kk * 256;        // 0..1535
            int n = j / 3;
            int c = j - 3 * n;
            spcl[j] = src[n * 48 + c];
        }
    }
    __syncthreads();

    // ---- build packed registers from smem ----
    const float* spcl = sred;
    unsigned long long nx2[NPAIR], ny2[NPAIR], nz2[NPAIR], uu2[NPAIR];
    float dmin[NCNT];
#pragma unroll
    for (int p = 0; p < NPAIR; p++) {
        int na = ((2 * p) * TX + x) * 3;
        int nb = ((2 * p + 1) * TX + x) * 3;
        float xa = spcl[na], ya = spcl[na + 1], za = spcl[na + 2];
        float xb = spcl[nb], yb = spcl[nb + 1], zb = spcl[nb + 2];
        PACK2(nx2[p], -2.0f * xa, -2.0f * xb);
        PACK2(ny2[p], -2.0f * ya, -2.0f * yb);
        PACK2(nz2[p], -2.0f * za, -2.0f * zb);
        PACK2(uu2[p], xa * xa + ya * ya + za * za,
                      xb * xb + yb * yb + zb * zb);
        dmin[2 * p] = 3.4e38f;
        dmin[2 * p + 1] = 3.4e38f;
    }
    __syncthreads();   // everyone done reading spcl before sred is rewritten

    // ---- hot loop: 32 s x 8 n per thread ----
#pragma unroll
    for (int k = 0; k < SCNT; k++) {
        const int s = y * SCNT + k;
        ulonglong2 ac = sAC[s];
        ulonglong2 dq = sDQ[s];
        float pm[NPAIR];
#pragma unroll
        for (int p = 0; p < NPAIR; p++) {
            unsigned long long t;
            ADD2(t, dq.y, uu2[p]);             // q + |x|^2
            FMA2(t, ac.x, nx2[p], t);          // -2 a x
            FMA2(t, ac.y, ny2[p], t);
            FMA2(t, dq.x, nz2[p], t);
            float f0, f1;
            UNPACK2(f0, f1, t);
            dmin[2 * p]     = fminf(dmin[2 * p], f0);
            dmin[2 * p + 1] = fminf(dmin[2 * p + 1], f1);
            pm[p] = fminf(f0, f1);
        }
        sminS[k * SPAD + tid] =
            fminf(fminf(pm[0], pm[1]), fminf(pm[2], pm[3]));
    }

    // ---- epilogue 1: dmin — combine the 4 y-slices via smem ----
#pragma unroll
    for (int j = 0; j < NCNT; j++) sred[y * NCHUNK + j * TX + x] = dmin[j];
    __syncthreads();

    float* d1out = g_d1T + (size_t)bm * NPTS + chunk * NCHUNK;
#pragma unroll
    for (int r = 0; r < 2; r++) {
        int nl = r * 256 + tid;
        float v = fminf(fminf(sred[0 * NCHUNK + nl], sred[1 * NCHUNK + nl]),
                        fminf(sred[2 * NCHUNK + nl], sred[3 * NCHUNK + nl]));
        d1out[nl] = v;
    }

    // ---- epilogue 2: smin — per s, min over its 64 contributing threads ----
    if (tid < SS) {
        const int kk = tid & 31;
        const int yy = tid >> 5;
        const float* rowp = sminS + kk * SPAD + 64 * yy;
        float v = rowp[0];
#pragma unroll
        for (int i = 1; i < 64; i++) v = fminf(v, rowp[i]);
        g_partmin[(size_t)bid * SS + tid] = v;
    }
}

// ---------------------------------------------------------------------------
// Kernel 2 (fused with the final combine):
//  blocks [0,128): per (b,n) SORT-FREE stick-breaking — for each i,
//    weight_i = p_i * prod_{j "before" i} (1-p_j), where "before" in the
//    stable argsort means d_j < d_i, or d_j == d_i && j < i (compile-time
//    <= vs < per pair). 240 independent cmp+sel+mul -> deep ILP, no serial
//    sort network. Identical arithmetic values to sort+cumprod.
//  blocks [128,160): colmean -> g_colmean.
//  LAST block (fence + atomic ticket) computes areas + final scalars.
// ---------------------------------------------------------------------------
__global__ __launch_bounds__(256) void k2(const float* __restrict__ probs,
                                          const float* __restrict__ size_,
                                          float* __restrict__ out, int out_size) {
    __shared__ float red[256];
    __shared__ int is_last;

    if (blockIdx.x < K2_SORT_BLOCKS) {
        const int idx = blockIdx.x * 256 + threadIdx.x;  // < B*N
        const int b = idx >> 11;
        const int n = idx & (NPTS - 1);

        float d[MM], p[MM], q[MM];
#pragma unroll
        for (int i = 0; i < MM; i++)
            d[i] = g_d1T[(size_t)(b * MM + i) * NPTS + n];
#pragma unroll
        for (int i = 0; i < MM; i++) {
            p[i] = probs[b * MM + i];
            q[i] = 1.0f - p[i];
        }

        float sum = 0.0f;
#pragma unroll
        for (int i = 0; i < MM; i++) {
            float w = d[i] * p[i];
#pragma unroll
            for (int j = 0; j < MM; j++) {
                if (j == i) continue;
                // stable order: j before i iff d[j] < d[i], ties broken by index
                bool before = (j < i) ? (d[j] <= d[i]) : (d[j] < d[i]);
                w *= before ? q[j] : 1.0f;
            }
            sum += w;
        }

        red[threadIdx.x] = sum;
        __syncthreads();
        for (int off = 128; off > 0; off >>= 1) {
            if (threadIdx.x < off) red[threadIdx.x] += red[threadIdx.x + off];
            __syncthreads();
        }
        if (threadIdx.x == 0) g_part1[blockIdx.x] = red[0];
    } else {
        const int bb = blockIdx.x - K2_SORT_BLOCKS;     // 0..31
        const int w = threadIdx.x >> 5;
        const int lane = threadIdx.x & 31;
        const int bm = bb * 8 + w;

        const float* pm = g_partmin + (size_t)bm * NSPLIT * SS;
        float sum = 0.0f;
#pragma unroll
        for (int i = 0; i < SS / 32; i++) {
            int s = lane + 32 * i;
            float mn = fminf(fminf(pm[0 * SS + s], pm[1 * SS + s]),
                             fminf(pm[2 * SS + s], pm[3 * SS + s]));
            if (mn >= 1e30f) mn = 0.0f;   // INF_CLAMP rule
            sum += mn;
        }
#pragma unroll
        for (int off = 16; off > 0; off >>= 1)
            sum += __shfl_down_sync(0xffffffffu, sum, off);
        if (lane == 0) g_colmean[bm] = sum * (1.0f / SS);
    }

    // ---- last-block election: the final combine ----
    __threadfence();
    if (threadIdx.x == 0) {
        unsigned t = atomicAdd(&g_ticket, 1u);
        is_last = (t == K2_TOTAL - 1);
    }
    __syncthreads();
    if (!is_last) return;

    const int tid = threadIdx.x;  // 256 == B*M
    const float FOUR_PI = 12.566370614359172f;
    __shared__ float area[256];
    __shared__ float p1_shared;
    const int b = tid >> 4;

    float s0 = size_[tid * 3 + 0];
    float s1 = size_[tid * 3 + 1];
    float s2 = size_[tid * 3 + 2];
    // sizes in [0.05, 1] -> strictly positive; fast MUFU pow is safe.
    float inner = (__powf(s0 * s1, 1.6f) + __powf(s0 * s2, 1.6f) + __powf(s1 * s2, 1.6f))
                  * (1.0f / 3.0f);
    float ar = FOUR_PI * __powf(inner, 0.625f);
    area[tid] = ar;
    __syncthreads();

    float sb = 0.0f;
#pragma unroll
    for (int j = 0; j < MM; j++) sb += area[b * MM + j];

    float contrib = g_colmean[tid] * probs[tid] * ((float)MM * ar / sb) * (1.0f / (BB * MM));

    red[tid] = (tid < K2_SORT_BLOCKS) ? g_part1[tid] : 0.0f;
    __syncthreads();
    for (int off = 128; off > 0; off >>= 1) {
        if (tid < off) red[tid] += red[tid + off];
        __syncthreads();
    }
    if (tid == 0) p1_shared = red[0];
    __syncthreads();

    red[tid] = contrib;
    __syncthreads();
    for (int off = 128; off > 0; off >>= 1) {
        if (tid < off) red[tid] += red[tid + off];
        __syncthreads();
    }

    if (tid == 0) {
        float pcl_to_prim = p1_shared * (1.0f / ((float)BB * (float)NPTS));
        float prim_to_pcl = red[0];
        float total = pcl_to_prim + prim_to_pcl;
        if (out_size > 0) out[0] = total;
        if (out_size > 1) out[1] = pcl_to_prim;
        if (out_size > 2) out[2] = prim_to_pcl;
        if (out_size > 3) out[3] = 0.0f;
        g_ticket = 0;   // reset for the next graph replay
    }
}

extern "C" void kernel_launch(void* const* d_in, const int* in_sizes, int n_in,
                              void* d_out, int out_size) {
    const float* pcl   = (const float*)d_in[0];  // (B, N, M, 3)
    const float* prim  = (const float*)d_in[1];  // (B, M, S, 3)
    const float* size_ = (const float*)d_in[2];  // (B, M, 3)
    const float* probs = (const float*)d_in[3];  // (B, M)

    k1<<<BB * MM * NSPLIT, TX * TY>>>(pcl, prim);
    k2<<<K2_TOTAL, 256>>>(probs, size_, (float*)d_out, out_size);
}